// round 14
// baseline (speedup 1.0000x reference)
#include <cuda_runtime.h>
#include <math.h>
#include <stdint.h>

#define N_    8192
#define H_    128
#define B_    100
#define K_    5
#define MAXN  160

// ---------------- persistent scratch ----------------
__device__ float g_Wh0[N_*H_];
__device__ float g_e0[N_], g_e1[N_];           // z0 . head0/head1
__device__ float g_d0[N_], g_d1[N_];           // z0 . tail0/tail1
__device__ int   g_nbr_idx[2*B_*MAXN];
__device__ float g_nbr_q[2*B_*MAXN];
__device__ int   g_nbr_cnt[2*B_];
__device__ int   g_first[N_];                  // first step a node is updated
__device__ float g_cmax[2*B_*H_];              // clean-neighbor max per (event,dim)
__device__ int   g_dirty_idx[2*B_*MAXN];
__device__ float g_dirty_q[2*B_*MAXN];
__device__ int   g_dirty_cnt[2*B_];
__device__ int   g_last[N_];
__device__ int   g_log_node[2*B_];
__device__ float g_log_z [2*B_*H_];
__device__ float g_log_wh[2*B_*H_];
__device__ float g_log_e0[2*B_], g_log_e1[2*B_], g_log_d0[2*B_], g_log_d1[2*B_];
__device__ float g_rec[B_*8];   // per step: z_u.{h0,h1,t0,t1}, z_v.{h0,h1,t0,t1}

// ---------------- prologue: Wh0 = z0 @ Wh_w.T + Wh_b ----------------
__global__ void k_wh0(const float* __restrict__ z0, const float* __restrict__ Whw,
                      const float* __restrict__ Whb) {
    extern __shared__ float sm_w[];
    float* Ws = sm_w;                 // 128*129
    float* zr = Ws + 128*129;         // 32*128
    int t = threadIdx.x;
    for (int idx = t; idx < 128*128; idx += 256)
        Ws[(idx>>7)*129 + (idx&127)] = Whw[idx];
    int r0 = blockIdx.x * 32;
    for (int idx = t; idx < 32*128; idx += 256)
        zr[idx] = z0[(size_t)r0*H_ + idx];
    __syncthreads();
    int rr = t >> 7, d = t & 127;
    for (int r = rr; r < 32; r += 2) {
        float a0=0.f,a1=0.f,a2=0.f,a3=0.f;
        #pragma unroll 8
        for (int k = 0; k < 128; k += 4) {
            a0 += zr[r*128+k  ]*Ws[d*129+k  ];
            a1 += zr[r*128+k+1]*Ws[d*129+k+1];
            a2 += zr[r*128+k+2]*Ws[d*129+k+2];
            a3 += zr[r*128+k+3]*Ws[d*129+k+3];
        }
        g_Wh0[(size_t)(r0+r)*H_ + d] = (a0+a1)+(a2+a3) + Whb[d];
    }
}

// ---------------- prologue: base dot products ----------------
__global__ void k_dots(const float* __restrict__ z0, const float* __restrict__ om0w,
                       const float* __restrict__ om1w) {
    int w = threadIdx.x >> 5, l = threadIdx.x & 31;
    int row = blockIdx.x * 8 + w;
    const float* zrp = z0 + (size_t)row * H_;
    float p0=0.f,p1=0.f,p2=0.f,p3=0.f;
    #pragma unroll
    for (int k = l; k < 128; k += 32) {
        float zv = zrp[k];
        p0 += zv * om0w[k];
        p1 += zv * om1w[k];
        p2 += zv * om0w[128+k];
        p3 += zv * om1w[128+k];
    }
    #pragma unroll
    for (int o = 16; o; o >>= 1) {
        p0 += __shfl_down_sync(0xffffffffu, p0, o);
        p1 += __shfl_down_sync(0xffffffffu, p1, o);
        p2 += __shfl_down_sync(0xffffffffu, p2, o);
        p3 += __shfl_down_sync(0xffffffffu, p3, o);
    }
    if (l == 0) { g_e0[row]=p0; g_e1[row]=p1; g_d0[row]=p2; g_d1[row]=p3; }
}

// ---------------- prologue: compact neighbor lists ----------------
__global__ void k_nbr(const int* __restrict__ u, const int* __restrict__ v,
                      const float* __restrict__ A, const float* __restrict__ S) {
    __shared__ int   cnt;
    __shared__ float part[256];
    int b = blockIdx.x;              // b = 2*i + s ; s==0 -> v_i, s==1 -> u_i
    int i = b >> 1, s = b & 1;
    int node = s ? u[i] : v[i];
    if (threadIdx.x == 0) cnt = 0;
    __syncthreads();
    const float* Arow = A + (size_t)node * N_;
    const float* Srow = S + (size_t)node * N_;
    float local = 0.f;
    for (int j = threadIdx.x; j < N_; j += 256) {
        if (Arow[j] > 0.f) {
            float e = expf(Srow[j]);
            int p = atomicAdd(&cnt, 1);
            if (p < MAXN) { g_nbr_idx[b*MAXN+p] = j; g_nbr_q[b*MAXN+p] = e; }
            local += e;
        }
    }
    part[threadIdx.x] = local;
    __syncthreads();
    for (int off = 128; off; off >>= 1) {
        if (threadIdx.x < off) part[threadIdx.x] += part[threadIdx.x + off];
        __syncthreads();
    }
    float inv = 1.0f / (part[0] + 1e-7f);
    int c = min(cnt, MAXN);
    for (int p = threadIdx.x; p < c; p += 256) g_nbr_q[b*MAXN+p] *= inv;
    if (threadIdx.x == 0) g_nbr_cnt[b] = c;
}

// ---------------- prologue: first-update times ----------------
__global__ void k_finit() {
    int idx = blockIdx.x * 1024 + threadIdx.x;
    if (idx < N_) g_first[idx] = 0x7fffffff;
}
__global__ void k_fset(const int* __restrict__ u, const int* __restrict__ v) {
    int i = threadIdx.x;
    if (i < B_) {
        atomicMin(&g_first[u[i]], i);
        atomicMin(&g_first[v[i]], i);
    }
}

// ---------------- prologue: clean-neighbor max + dirty compaction ----------
__global__ void k_cmax() {
    __shared__ int   sj[MAXN];
    __shared__ float sqv[MAXN];
    __shared__ int   sf[MAXN];
    int b = blockIdx.x, i = b >> 1;
    int tid = threadIdx.x;
    int cnt = g_nbr_cnt[b];
    for (int n = tid; n < cnt; n += 256) {
        int j = g_nbr_idx[b*MAXN+n];
        sj[n]  = j;
        sqv[n] = g_nbr_q[b*MAXN+n];
        sf[n]  = (g_first[j] < i) ? 1 : 0;
    }
    __syncthreads();
    if (tid < 128) {
        int d = tid;
        float mx = -3.4e38f;
        for (int n = 0; n < cnt; n++)
            if (!sf[n]) mx = fmaxf(mx, sqv[n] * g_Wh0[(size_t)sj[n]*H_ + d]);
        g_cmax[b*H_ + d] = mx;
    } else if (tid == 128) {
        int c = 0;
        for (int n = 0; n < cnt; n++)
            if (sf[n]) {
                g_dirty_idx[b*MAXN + c] = sj[n];
                g_dirty_q  [b*MAXN + c] = sqv[n];
                c++;
            }
        g_dirty_cnt[b] = c;
    }
}

// ---------------- phase 1: sequential scan (1 block, 1024 threads) ----------
__global__ void __launch_bounds__(1024, 1)
k_seq(const int* __restrict__ u, const int* __restrict__ v,
      const float* __restrict__ time_diff, const float* __restrict__ z0,
      const float* __restrict__ om0w, const float* __restrict__ om1w,
      const float* __restrict__ Whw, const float* __restrict__ Whb,
      const float* __restrict__ Wsw, const float* __restrict__ Wsb,
      const float* __restrict__ Wrw, const float* __restrict__ Wrb,
      const float* __restrict__ Wtw, const float* __restrict__ Wtb)
{
    extern __shared__ char smraw[];
    const float** sptr = (const float**)smraw;        // 2*MAXN resolved dirty rows
    float* sq  = (float*)(sptr + 2*MAXN);             // 2*MAXN dirty q
    float* Wss = sq + 2*MAXN;                         // 128*129
    float* Wrs = Wss + 128*129;                       // 128*129
    float* Whs = Wrs + 128*129;                       // 128*129
    float* zs  = Whs + 128*129;                       // 2*128 (z_u, z_v)
    float* hss = zs + 256;                            // 2*128 (struct(v), struct(u))
    float* hh  = hss + 256;                           // 2*128 (z_upd)
    float* red = hh + 256;                            // 2048
    float* oms = red + 2048;                          // 512: head0,head1,tail0,tail1
    float* bsm = oms + 512;                           // 1024: Whb,Wsb,Wrb,Wtb,Wtw
    float* tds = bsm + 1024;                          // 800
    float* cms = tds + 800;                           // 256 clean max
    int*   us  = (int*)(cms + 256);                   // 128
    int*   vs  = us + 128;                            // 128
    int*   sdc = vs + 128;                            // 2 dirty counts
    int*   scc = sdc + 2;                             // 2 neighbor counts
    const int tid = threadIdx.x;

    for (int idx = tid; idx < 128*128; idx += 1024) {
        int r = idx >> 7, c = idx & 127;
        Wss[r*129+c] = Wsw[idx];
        Wrs[r*129+c] = Wrw[idx];
        Whs[r*129+c] = Whw[idx];
    }
    if (tid < 128) {
        oms[tid]     = om0w[tid];
        oms[128+tid] = om1w[tid];
        oms[256+tid] = om0w[128+tid];
        oms[384+tid] = om1w[128+tid];
        bsm[tid]     = Whb[tid];
        bsm[128+tid] = Wsb[tid];
        bsm[256+tid] = Wrb[tid];
        bsm[384+tid] = Wtb[tid];
    }
    if (tid < 512) bsm[512+tid] = Wtw[tid];
    if (tid < 800) tds[tid] = time_diff[tid];
    if (tid < B_)  { us[tid] = u[tid]; vs[tid] = v[tid]; }
    for (int idx = tid; idx < N_; idx += 1024) g_last[idx] = -1;
    __syncthreads();

    for (int i = 0; i < B_; i++) {
        const int ui = us[i], vi = vs[i];

        // ---- stage A: stage zs, clean-max, dirty rows ----
        if (tid < 256) {
            int s = tid >> 7, d = tid & 127;
            int node = s ? vi : ui;              // zs row0 = z_u, row1 = z_v
            int li = g_last[node];
            zs[tid] = (li >= 0) ? g_log_z[(size_t)li*H_ + d]
                                : z0[(size_t)node*H_ + d];
        } else if (tid < 512) {
            int t2 = tid - 256;                  // s = t2>>7, d = t2&127
            cms[t2] = g_cmax[(2*i + (t2>>7))*H_ + (t2&127)];
        } else if (tid < 832) {
            int slot = tid - 512;                // 0..319
            int s = slot / MAXN, n = slot - s*MAXN;
            int b = 2*i + s;
            if (n < g_dirty_cnt[b]) {
                int j  = g_dirty_idx[b*MAXN+n];
                int li = g_last[j];
                sptr[slot] = (li >= 0) ? (g_log_wh + (size_t)li*H_)
                                       : (g_Wh0    + (size_t)j *H_);
                sq[slot] = g_dirty_q[b*MAXN+n];
            }
        } else if (tid >= 1020) {
            int s = tid - 1020;
            if (s < 2) sdc[s] = g_dirty_cnt[2*i+s];
            else       scc[s-2] = g_nbr_cnt[2*i+s-2];
        }
        __syncthreads();

        // ---- stage B: struct via clean-max + dirty corrections; zs dots ----
        if (tid < 256) {
            int s = tid >> 7, d = tid & 127;
            float mx = cms[tid];
            int nd = sdc[s];
            for (int n = 0; n < nd; n++)
                mx = fmaxf(mx, sq[s*MAXN+n] * sptr[s*MAXN+n][d]);
            hss[tid] = (scc[s] > 0) ? (1.0f/(1.0f+__expf(-mx))) : 0.0f;
        } else if (tid < 512) {
            int w2 = (tid >> 5) - 8, l = tid & 31;       // w2 in 0..7
            const float* va = zs + ((w2 >> 2) & 1)*128;  // 0-3: z_u, 4-7: z_v
            const float* vo = oms + (w2 & 3)*128;
            float p = va[l]*vo[l] + va[l+32]*vo[l+32]
                    + va[l+64]*vo[l+64] + va[l+96]*vo[l+96];
            #pragma unroll
            for (int o = 16; o; o >>= 1) p += __shfl_down_sync(0xffffffffu, p, o);
            if (l == 0) g_rec[i*8 + w2] = p;
        }
        __syncthreads();

        // ---- stage D: h partials, 8-way k-split, both rows per thread ----
        {
            int g = tid >> 7, d = tid & 127;
            int k0 = g*16;
            float a0 = 0.f, a1 = 0.f;
            #pragma unroll
            for (int k = 0; k < 16; k++) {
                int kk = k0 + k;
                float ws = Wss[d*129+kk], wr = Wrs[d*129+kk];
                a0 += hss[kk]*ws     + zs[kk]*wr;
                a1 += hss[128+kk]*ws + zs[128+kk]*wr;
            }
            red[g*256 + d]       = a0;
            red[g*256 + 128 + d] = a1;
        }
        __syncthreads();

        // ---- stage D2: combine -> z_upd ----
        if (tid < 256) {
            int r = tid >> 7, d = tid & 127;
            float acc = 0.f;
            #pragma unroll
            for (int g = 0; g < 8; g++) acc += red[g*256 + tid];
            acc += bsm[128+d] + bsm[256+d] + bsm[384+d];
            acc += (tds[i*8 + r*4 + 0] / 50.0f) * bsm[512 + d*4 + 0];
            acc += (tds[i*8 + r*4 + 1] /  7.0f) * bsm[512 + d*4 + 1];
            acc += (tds[i*8 + r*4 + 2] / 15.0f) * bsm[512 + d*4 + 2];
            acc += (tds[i*8 + r*4 + 3] / 15.0f) * bsm[512 + d*4 + 3];
            hh[tid] = 1.0f/(1.0f+__expf(-acc));
        }
        __syncthreads();

        // ---- stage E: Wh partials for z_upd rows ----
        {
            int g = tid >> 7, d = tid & 127;
            int k0 = g*16;
            float a0 = 0.f, a1 = 0.f;
            #pragma unroll
            for (int k = 0; k < 16; k++) {
                int kk = k0 + k;
                float wh = Whs[d*129+kk];
                a0 += hh[kk]*wh;
                a1 += hh[128+kk]*wh;
            }
            red[g*256 + d]       = a0;
            red[g*256 + 128 + d] = a1;
        }
        __syncthreads();

        // ---- stage E2: write Wh log rows, hh dots, log_z, bookkeeping ----
        if (tid < 256) {
            int d = tid & 127;
            float acc = bsm[d];
            #pragma unroll
            for (int g = 0; g < 8; g++) acc += red[g*256 + tid];
            g_log_wh[(size_t)(2*i + (tid>>7))*H_ + d] = acc;
        } else if (tid < 512) {
            int w2 = (tid >> 5) - 8, l = tid & 31;
            const float* va = hh + ((w2 >> 2) & 1)*128;
            const float* vo = oms + (w2 & 3)*128;
            float p = va[l]*vo[l] + va[l+32]*vo[l+32]
                    + va[l+64]*vo[l+64] + va[l+96]*vo[l+96];
            #pragma unroll
            for (int o = 16; o; o >>= 1) p += __shfl_down_sync(0xffffffffu, p, o);
            if (l == 0) {
                int e = 2*i + (w2 >> 2);
                int which = w2 & 3;
                if      (which == 0) g_log_e0[e] = p;
                else if (which == 1) g_log_e1[e] = p;
                else if (which == 2) g_log_d0[e] = p;
                else                 g_log_d1[e] = p;
            }
        } else if (tid < 768) {
            g_log_z[(size_t)2*i*H_ + (tid - 512)] = hh[tid - 512];
        } else if (tid == 1023) {
            g_log_node[2*i]   = ui;
            g_log_node[2*i+1] = vi;
            g_last[ui] = 2*i;
            g_last[vi] = 2*i + 1;    // v wins if ui==vi (matches .at[u] then .at[v])
        }
        __syncthreads();
    }
}

// ---------------- phase 2: per-step hawkes readouts ----------------
__device__ __forceinline__ float hawkes_f(float g, float td, float inv, float ps,
                                          float al, float wt) {
    float gp = fminf(fmaxf(g * inv, -75.f), 75.f);
    return ps * log1pf(expf(gp)) + al * expf(-wt * (td * 1e-4f));
}

__global__ void __launch_bounds__(1024, 1)
k_lam(const int* __restrict__ u, const int* __restrict__ v,
      const int* __restrict__ etA, const int* __restrict__ neg,
      const float* __restrict__ tbar, const float* __restrict__ tarr,
      const float* __restrict__ w_t, const float* __restrict__ alpha,
      const float* __restrict__ psi,
      const float* __restrict__ om0b, const float* __restrict__ om1b,
      float* __restrict__ out)
{
    __shared__ float dcur[N_];
    __shared__ float s_red[1024];

    const int i = blockIdx.x;
    const int t = threadIdx.x;
    const int ui = u[i], vi = v[i], et = etA[i];
    const float ps = psi[et], al = alpha[et], wt = w_t[et];
    const float bb = et ? om1b[0] : om0b[0];
    const float inv = 1.0f / (ps + 1e-7f);
    const float t_i = tarr[i];
    const float* tb = tbar + (size_t)i * N_;
    const float tb_u = tb[ui], tb_v = tb[vi];
    const float cu_h = g_rec[i*8 + et];          // z_u . head_et
    const float cv_h = g_rec[i*8 + 4 + et];      // z_v . head_et
    const float cv_t = g_rec[i*8 + 6 + et];      // z_v . tail_et
    const float* dbase = et ? g_d1 : g_d0;
    const float* ebase = et ? g_e1 : g_e0;
    const float* lgd = et ? g_log_d1 : g_log_d0;
    const float* lge = et ? g_log_e1 : g_log_e0;
    const int nk = 2*i;

    for (int j = t; j < N_; j += 1024) dcur[j] = dbase[j];
    __syncthreads();
    if (t == 0)
        for (int k = 0; k < nk; k++) dcur[g_log_node[k]] = lgd[k];
    __syncthreads();

    // lam_sum over 2N terms, mask j != u_i, j != v_i
    float acc = 0.f;
    for (int j = t; j < N_; j += 1024) {
        if (j == ui || j == vi) continue;
        float d   = dcur[j];
        float tbj = tb[j];
        acc += hawkes_f(cu_h + d + bb, t_i - fmaxf(tb_u, tbj), inv, ps, al, wt);
        acc += hawkes_f(cv_h + d + bb, t_i - fmaxf(tb_v, tbj), inv, ps, al, wt);
    }
    s_red[t] = acc;
    __syncthreads();
    for (int off = 512; off; off >>= 1) {
        if (t < off) s_red[t] += s_red[t+off];
        __syncthreads();
    }
    if (t == 0) out[i*12 + 11] = s_red[0];

    // lam_pos (t==0) and lam_neg (t=1..10)
    if (t < 11) {
        float g, td;
        if (t == 0) {
            g  = cu_h + cv_t + bb;
            td = t_i - fmaxf(tb_u, tb_v);
        } else if (t <= 5) {
            int vn = neg[i*10 + t - 1];
            g  = cu_h + dcur[vn] + bb;
            td = t_i - fmaxf(tb_u, tb[vn]);
        } else {
            int un = neg[i*10 + t - 1];
            float e = ebase[un];
            for (int k = nk - 1; k >= 0; k--)
                if (g_log_node[k] == un) { e = lge[k]; break; }
            g  = e + cv_t + bb;
            td = t_i - fmaxf(tb[un], tb_v);
        }
        out[i*12 + t] = hawkes_f(g, td, inv, ps, al, wt);
    }
}

extern "C" void kernel_launch(void* const* d_in, const int* in_sizes, int n_in,
                              void* d_out, int out_size) {
    const int*   u    = (const int*)  d_in[0];
    const int*   v    = (const int*)  d_in[1];
    const int*   et   = (const int*)  d_in[2];
    const int*   neg  = (const int*)  d_in[3];
    const float* td   = (const float*)d_in[4];
    const float* tbar = (const float*)d_in[5];
    const float* tarr = (const float*)d_in[6];
    const float* z0   = (const float*)d_in[7];
    const float* A    = (const float*)d_in[8];
    const float* S    = (const float*)d_in[9];
    const float* w_t  = (const float*)d_in[10];
    const float* alpha= (const float*)d_in[11];
    const float* psi  = (const float*)d_in[12];
    const float* om0w = (const float*)d_in[13];
    const float* om0b = (const float*)d_in[14];
    const float* om1w = (const float*)d_in[15];
    const float* om1b = (const float*)d_in[16];
    const float* Whw  = (const float*)d_in[17];
    const float* Whb  = (const float*)d_in[18];
    const float* Wsw  = (const float*)d_in[19];
    const float* Wsb  = (const float*)d_in[20];
    const float* Wrw  = (const float*)d_in[21];
    const float* Wrb  = (const float*)d_in[22];
    const float* Wtw  = (const float*)d_in[23];
    const float* Wtb  = (const float*)d_in[24];
    float* out = (float*)d_out;

    const int smem_wh0 = (128*129 + 32*128) * 4;
    const int smem_seq = 2*MAXN*8 + 2*MAXN*4 + 3*128*129*4
                       + (256*3 + 2048 + 512 + 1024 + 800 + 256)*4
                       + (128+128+2+2)*4;

    cudaFuncSetAttribute(k_wh0, cudaFuncAttributeMaxDynamicSharedMemorySize, smem_wh0);
    cudaFuncSetAttribute(k_seq, cudaFuncAttributeMaxDynamicSharedMemorySize, smem_seq);

    k_wh0<<<N_/32, 256, smem_wh0>>>(z0, Whw, Whb);
    k_dots<<<N_/8, 256>>>(z0, om0w, om1w);
    k_finit<<<(N_+1023)/1024, 1024>>>();
    k_nbr<<<2*B_, 256>>>(u, v, A, S);
    k_fset<<<1, 128>>>(u, v);
    k_cmax<<<2*B_, 256>>>();
    k_seq<<<1, 1024, smem_seq>>>(u, v, td, z0, om0w, om1w,
                                 Whw, Whb, Wsw, Wsb, Wrw, Wrb, Wtw, Wtb);
    k_lam<<<B_, 1024>>>(u, v, et, neg, tbar, tarr, w_t, alpha, psi,
                        om0b, om1b, out);
}

// round 15
// speedup vs baseline: 1.0345x; 1.0345x over previous
#include <cuda_runtime.h>
#include <math.h>
#include <stdint.h>

#define N_    8192
#define H_    128
#define B_    100
#define K_    5
#define MAXN  160

// swizzled float4 index for weight matrices: row d (0..127), k4 (0..31)
#define WIDX(d,k4) (((d) << 5) + ((k4) ^ ((d) & 7)))

// ---------------- persistent scratch ----------------
__device__ float g_Wh0[N_*H_];
__device__ float g_e0[N_], g_e1[N_];           // z0 . head0/head1
__device__ float g_d0[N_], g_d1[N_];           // z0 . tail0/tail1
__device__ int   g_nbr_idx[2*B_*MAXN];
__device__ float g_nbr_q[2*B_*MAXN];
__device__ int   g_nbr_cnt[2*B_];
__device__ int   g_first[N_];                  // first step a node is updated
__device__ float g_cmax[2*B_*H_];              // clean-neighbor max per (event,dim)
__device__ int   g_dirty_idx[2*B_*MAXN];
__device__ float g_dirty_q[2*B_*MAXN];
__device__ int   g_dirty_cnt[2*B_];
__device__ int   g_last[N_];
__device__ int   g_log_node[2*B_];
__device__ float g_log_z [2*B_*H_];
__device__ float g_log_wh[2*B_*H_];
__device__ float g_log_e0[2*B_], g_log_e1[2*B_], g_log_d0[2*B_], g_log_d1[2*B_];
__device__ float g_rec[B_*8];   // per step: z_u.{h0,h1,t0,t1}, z_v.{h0,h1,t0,t1}

// ---------------- prologue: Wh0 = z0 @ Wh_w.T + Wh_b ----------------
__global__ void k_wh0(const float* __restrict__ z0, const float* __restrict__ Whw,
                      const float* __restrict__ Whb) {
    extern __shared__ float sm_w[];
    float* Ws = sm_w;                 // 128*129
    float* zr = Ws + 128*129;         // 32*128
    int t = threadIdx.x;
    for (int idx = t; idx < 128*128; idx += 256)
        Ws[(idx>>7)*129 + (idx&127)] = Whw[idx];
    int r0 = blockIdx.x * 32;
    for (int idx = t; idx < 32*128; idx += 256)
        zr[idx] = z0[(size_t)r0*H_ + idx];
    __syncthreads();
    int rr = t >> 7, d = t & 127;
    for (int r = rr; r < 32; r += 2) {
        float a0=0.f,a1=0.f,a2=0.f,a3=0.f;
        #pragma unroll 8
        for (int k = 0; k < 128; k += 4) {
            a0 += zr[r*128+k  ]*Ws[d*129+k  ];
            a1 += zr[r*128+k+1]*Ws[d*129+k+1];
            a2 += zr[r*128+k+2]*Ws[d*129+k+2];
            a3 += zr[r*128+k+3]*Ws[d*129+k+3];
        }
        g_Wh0[(size_t)(r0+r)*H_ + d] = (a0+a1)+(a2+a3) + Whb[d];
    }
}

// ---------------- prologue: base dot products ----------------
__global__ void k_dots(const float* __restrict__ z0, const float* __restrict__ om0w,
                       const float* __restrict__ om1w) {
    int w = threadIdx.x >> 5, l = threadIdx.x & 31;
    int row = blockIdx.x * 8 + w;
    const float* zrp = z0 + (size_t)row * H_;
    float p0=0.f,p1=0.f,p2=0.f,p3=0.f;
    #pragma unroll
    for (int k = l; k < 128; k += 32) {
        float zv = zrp[k];
        p0 += zv * om0w[k];
        p1 += zv * om1w[k];
        p2 += zv * om0w[128+k];
        p3 += zv * om1w[128+k];
    }
    #pragma unroll
    for (int o = 16; o; o >>= 1) {
        p0 += __shfl_down_sync(0xffffffffu, p0, o);
        p1 += __shfl_down_sync(0xffffffffu, p1, o);
        p2 += __shfl_down_sync(0xffffffffu, p2, o);
        p3 += __shfl_down_sync(0xffffffffu, p3, o);
    }
    if (l == 0) { g_e0[row]=p0; g_e1[row]=p1; g_d0[row]=p2; g_d1[row]=p3; }
}

// ---------------- prologue: compact neighbor lists ----------------
__global__ void k_nbr(const int* __restrict__ u, const int* __restrict__ v,
                      const float* __restrict__ A, const float* __restrict__ S) {
    __shared__ int   cnt;
    __shared__ float part[512];
    int b = blockIdx.x;              // b = 2*i + s ; s==0 -> v_i, s==1 -> u_i
    int i = b >> 1, s = b & 1;
    int node = s ? u[i] : v[i];
    if (threadIdx.x == 0) cnt = 0;
    __syncthreads();
    const float* Arow = A + (size_t)node * N_;
    const float* Srow = S + (size_t)node * N_;
    float local = 0.f;
    for (int j = threadIdx.x; j < N_; j += 512) {
        if (Arow[j] > 0.f) {
            float e = expf(Srow[j]);
            int p = atomicAdd(&cnt, 1);
            if (p < MAXN) { g_nbr_idx[b*MAXN+p] = j; g_nbr_q[b*MAXN+p] = e; }
            local += e;
        }
    }
    part[threadIdx.x] = local;
    __syncthreads();
    for (int off = 256; off; off >>= 1) {
        if (threadIdx.x < off) part[threadIdx.x] += part[threadIdx.x + off];
        __syncthreads();
    }
    float inv = 1.0f / (part[0] + 1e-7f);
    int c = min(cnt, MAXN);
    for (int p = threadIdx.x; p < c; p += 512) g_nbr_q[b*MAXN+p] *= inv;
    if (threadIdx.x == 0) g_nbr_cnt[b] = c;
}

// ---------------- prologue: first-update times ----------------
__global__ void k_finit() {
    int idx = blockIdx.x * 1024 + threadIdx.x;
    if (idx < N_) g_first[idx] = 0x7fffffff;
}
__global__ void k_fset(const int* __restrict__ u, const int* __restrict__ v) {
    int i = threadIdx.x;
    if (i < B_) {
        atomicMin(&g_first[u[i]], i);
        atomicMin(&g_first[v[i]], i);
    }
}

// ---------------- prologue: clean-neighbor max + dirty compaction ----------
__global__ void k_cmax() {
    __shared__ int   sj[MAXN];
    __shared__ float sqv[MAXN];
    __shared__ int   sf[MAXN];
    int b = blockIdx.x, i = b >> 1;
    int tid = threadIdx.x;
    int cnt = g_nbr_cnt[b];
    for (int n = tid; n < cnt; n += 256) {
        int j = g_nbr_idx[b*MAXN+n];
        sj[n]  = j;
        sqv[n] = g_nbr_q[b*MAXN+n];
        sf[n]  = (g_first[j] < i) ? 1 : 0;
    }
    __syncthreads();
    if (tid < 128) {
        int d = tid;
        float mx = -3.4e38f;
        for (int n = 0; n < cnt; n++)
            if (!sf[n]) mx = fmaxf(mx, sqv[n] * g_Wh0[(size_t)sj[n]*H_ + d]);
        g_cmax[b*H_ + d] = mx;
    } else if (tid == 128) {
        int c = 0;
        for (int n = 0; n < cnt; n++)
            if (sf[n]) {
                g_dirty_idx[b*MAXN + c] = sj[n];
                g_dirty_q  [b*MAXN + c] = sqv[n];
                c++;
            }
        g_dirty_cnt[b] = c;
    }
}

// ---------------- phase 1: sequential scan (1 block, 1024 threads) ----------
__global__ void __launch_bounds__(1024, 1)
k_seq(const int* __restrict__ u, const int* __restrict__ v,
      const float* __restrict__ time_diff, const float* __restrict__ z0,
      const float* __restrict__ om0w, const float* __restrict__ om1w,
      const float* __restrict__ Whw, const float* __restrict__ Whb,
      const float* __restrict__ Wsw, const float* __restrict__ Wsb,
      const float* __restrict__ Wrw, const float* __restrict__ Wrb,
      const float* __restrict__ Wtw, const float* __restrict__ Wtb)
{
    extern __shared__ char smraw[];
    const float** sptr = (const float**)smraw;        // 2*MAXN resolved dirty rows
    float* sq  = (float*)(sptr + 2*MAXN);             // 2*MAXN dirty q
    float* Wss = sq + 2*MAXN;                         // 128*128 swizzled f4
    float* Wrs = Wss + 128*128;                       // 128*128 swizzled f4
    float* Whs = Wrs + 128*128;                       // 128*128 swizzled f4
    float* zs  = Whs + 128*128;                       // 2*128 (z_u, z_v)
    float* hss = zs + 256;                            // 2*128 (struct(v), struct(u))
    float* hh  = hss + 256;                           // 2*128 (z_upd)
    float* red = hh + 256;                            // 3072 (0..2047 Ws/Wh, 2048.. Wr)
    float* oms = red + 3072;                          // 512: head0,head1,tail0,tail1
    float* bsm = oms + 512;                           // 1024: Whb,Wsb,Wrb,Wtb,Wtw
    float* tds = bsm + 1024;                          // 800
    float* cms = tds + 800;                           // 256 clean max
    int*   us  = (int*)(cms + 256);                   // 128
    int*   vs  = us + 128;                            // 128
    int*   sdc = vs + 128;                            // 2 dirty counts
    int*   scc = sdc + 2;                             // 2 neighbor counts
    const int tid = threadIdx.x;

    // swizzled store: element (r,c) -> float index 4*WIDX(r,c>>2) + (c&3)
    for (int idx = tid; idx < 128*128; idx += 1024) {
        int r = idx >> 7, c = idx & 127;
        int fi = 4*WIDX(r, c>>2) + (c&3);
        Wss[fi] = Wsw[idx];
        Wrs[fi] = Wrw[idx];
        Whs[fi] = Whw[idx];
    }
    if (tid < 128) {
        oms[tid]     = om0w[tid];
        oms[128+tid] = om1w[tid];
        oms[256+tid] = om0w[128+tid];
        oms[384+tid] = om1w[128+tid];
        bsm[tid]     = Whb[tid];
        bsm[128+tid] = Wsb[tid];
        bsm[256+tid] = Wrb[tid];
        bsm[384+tid] = Wtb[tid];
    }
    if (tid < 512) bsm[512+tid] = Wtw[tid];
    if (tid < 800) tds[tid] = time_diff[tid];
    if (tid < B_)  { us[tid] = u[tid]; vs[tid] = v[tid]; }
    for (int idx = tid; idx < N_; idx += 1024) g_last[idx] = -1;
    __syncthreads();

    const float4* Ws4 = (const float4*)Wss;
    const float4* Wr4 = (const float4*)Wrs;
    const float4* Wh4 = (const float4*)Whs;
    const float4* z4  = (const float4*)zs;
    const float4* h4  = (const float4*)hss;
    const float4* u4  = (const float4*)hh;

    for (int i = 0; i < B_; i++) {
        const int ui = us[i], vi = vs[i];

        // ---- stage A: stage zs, clean-max, dirty rows ----
        if (tid < 256) {
            int s = tid >> 7, d = tid & 127;
            int node = s ? vi : ui;              // zs row0 = z_u, row1 = z_v
            int li = g_last[node];
            zs[tid] = (li >= 0) ? g_log_z[(size_t)li*H_ + d]
                                : z0[(size_t)node*H_ + d];
        } else if (tid < 512) {
            int t2 = tid - 256;                  // s = t2>>7, d = t2&127
            cms[t2] = g_cmax[(2*i + (t2>>7))*H_ + (t2&127)];
        } else if (tid < 832) {
            int slot = tid - 512;                // 0..319
            int s = slot / MAXN, n = slot - s*MAXN;
            int b = 2*i + s;
            if (n < g_dirty_cnt[b]) {
                int j  = g_dirty_idx[b*MAXN+n];
                int li = g_last[j];
                sptr[slot] = (li >= 0) ? (g_log_wh + (size_t)li*H_)
                                       : (g_Wh0    + (size_t)j *H_);
                sq[slot] = g_dirty_q[b*MAXN+n];
            }
        } else if (tid >= 1020) {
            int s = tid - 1020;
            if (s < 2) sdc[s] = g_dirty_cnt[2*i+s];
            else       scc[s-2] = g_nbr_cnt[2*i+s-2];
        }
        __syncthreads();

        // ---- stage B: struct (w0-7) | zs dots (w8-15) | Wr partials (w16-31)
        if (tid < 256) {
            int s = tid >> 7, d = tid & 127;
            float mx = cms[tid];
            int nd = sdc[s];
            for (int n = 0; n < nd; n++)
                mx = fmaxf(mx, sq[s*MAXN+n] * sptr[s*MAXN+n][d]);
            hss[tid] = (scc[s] > 0) ? (1.0f/(1.0f+__expf(-mx))) : 0.0f;
        } else if (tid < 512) {
            int w2 = (tid >> 5) - 8, l = tid & 31;       // w2 in 0..7
            const float* va = zs + ((w2 >> 2) & 1)*128;  // 0-3: z_u, 4-7: z_v
            const float* vo = oms + (w2 & 3)*128;
            float p = va[l]*vo[l] + va[l+32]*vo[l+32]
                    + va[l+64]*vo[l+64] + va[l+96]*vo[l+96];
            #pragma unroll
            for (int o = 16; o; o >>= 1) p += __shfl_down_sync(0xffffffffu, p, o);
            if (l == 0) g_rec[i*8 + w2] = p;
        } else {
            int t2 = tid - 512;                  // 0..511
            int g2 = t2 >> 7, d = t2 & 127;      // g2 in 0..3, 32 k's each
            int k40 = g2*8;
            float a0 = 0.f, a1 = 0.f;
            #pragma unroll
            for (int k = 0; k < 8; k++) {
                float4 w  = Wr4[WIDX(d, k40+k)];
                float4 x0 = z4[k40+k];
                float4 x1 = z4[32+k40+k];
                a0 += w.x*x0.x + w.y*x0.y + w.z*x0.z + w.w*x0.w;
                a1 += w.x*x1.x + w.y*x1.y + w.z*x1.z + w.w*x1.w;
            }
            red[2048 + g2*256 + d]       = a0;
            red[2048 + g2*256 + 128 + d] = a1;
        }
        __syncthreads();

        // ---- stage D: Ws partials, 8-way k-split, both rows per thread ----
        {
            int g = tid >> 7, d = tid & 127;
            int k40 = g*4;                       // 16 k's = 4 float4
            float a0 = 0.f, a1 = 0.f;
            #pragma unroll
            for (int k = 0; k < 4; k++) {
                float4 w  = Ws4[WIDX(d, k40+k)];
                float4 x0 = h4[k40+k];
                float4 x1 = h4[32+k40+k];
                a0 += w.x*x0.x + w.y*x0.y + w.z*x0.z + w.w*x0.w;
                a1 += w.x*x1.x + w.y*x1.y + w.z*x1.z + w.w*x1.w;
            }
            red[g*256 + d]       = a0;
            red[g*256 + 128 + d] = a1;
        }
        __syncthreads();

        // ---- stage D2: combine -> z_upd ----
        if (tid < 256) {
            int r = tid >> 7, d = tid & 127;
            float acc = 0.f;
            #pragma unroll
            for (int g = 0; g < 8; g++) acc += red[g*256 + tid];
            #pragma unroll
            for (int g = 0; g < 4; g++) acc += red[2048 + g*256 + tid];
            acc += bsm[128+d] + bsm[256+d] + bsm[384+d];
            acc += (tds[i*8 + r*4 + 0] / 50.0f) * bsm[512 + d*4 + 0];
            acc += (tds[i*8 + r*4 + 1] /  7.0f) * bsm[512 + d*4 + 1];
            acc += (tds[i*8 + r*4 + 2] / 15.0f) * bsm[512 + d*4 + 2];
            acc += (tds[i*8 + r*4 + 3] / 15.0f) * bsm[512 + d*4 + 3];
            hh[tid] = 1.0f/(1.0f+__expf(-acc));
        }
        __syncthreads();

        // ---- stage E: Wh partials for z_upd rows ----
        {
            int g = tid >> 7, d = tid & 127;
            int k40 = g*4;
            float a0 = 0.f, a1 = 0.f;
            #pragma unroll
            for (int k = 0; k < 4; k++) {
                float4 w  = Wh4[WIDX(d, k40+k)];
                float4 x0 = u4[k40+k];
                float4 x1 = u4[32+k40+k];
                a0 += w.x*x0.x + w.y*x0.y + w.z*x0.z + w.w*x0.w;
                a1 += w.x*x1.x + w.y*x1.y + w.z*x1.z + w.w*x1.w;
            }
            red[g*256 + d]       = a0;
            red[g*256 + 128 + d] = a1;
        }
        __syncthreads();

        // ---- stage E2: write Wh log rows, hh dots, log_z, bookkeeping ----
        if (tid < 256) {
            int d = tid & 127;
            float acc = bsm[d];
            #pragma unroll
            for (int g = 0; g < 8; g++) acc += red[g*256 + tid];
            g_log_wh[(size_t)(2*i + (tid>>7))*H_ + d] = acc;
        } else if (tid < 512) {
            int w2 = (tid >> 5) - 8, l = tid & 31;
            const float* va = hh + ((w2 >> 2) & 1)*128;
            const float* vo = oms + (w2 & 3)*128;
            float p = va[l]*vo[l] + va[l+32]*vo[l+32]
                    + va[l+64]*vo[l+64] + va[l+96]*vo[l+96];
            #pragma unroll
            for (int o = 16; o; o >>= 1) p += __shfl_down_sync(0xffffffffu, p, o);
            if (l == 0) {
                int e = 2*i + (w2 >> 2);
                int which = w2 & 3;
                if      (which == 0) g_log_e0[e] = p;
                else if (which == 1) g_log_e1[e] = p;
                else if (which == 2) g_log_d0[e] = p;
                else                 g_log_d1[e] = p;
            }
        } else if (tid < 768) {
            g_log_z[(size_t)2*i*H_ + (tid - 512)] = hh[tid - 512];
        } else if (tid == 1023) {
            g_log_node[2*i]   = ui;
            g_log_node[2*i+1] = vi;
            g_last[ui] = 2*i;
            g_last[vi] = 2*i + 1;    // v wins if ui==vi (matches .at[u] then .at[v])
        }
        __syncthreads();
    }
}

// ---------------- phase 2: per-step hawkes readouts ----------------
__device__ __forceinline__ float hawkes_f(float g, float td, float inv, float ps,
                                          float al, float wt) {
    float gp = fminf(fmaxf(g * inv, -75.f), 75.f);
    return ps * __logf(1.0f + __expf(gp)) + al * __expf(-wt * (td * 1e-4f));
}

__global__ void __launch_bounds__(1024, 1)
k_lam(const int* __restrict__ u, const int* __restrict__ v,
      const int* __restrict__ etA, const int* __restrict__ neg,
      const float* __restrict__ tbar, const float* __restrict__ tarr,
      const float* __restrict__ w_t, const float* __restrict__ alpha,
      const float* __restrict__ psi,
      const float* __restrict__ om0b, const float* __restrict__ om1b,
      float* __restrict__ out)
{
    __shared__ float dcur[N_];
    __shared__ float s_red[1024];

    const int i = blockIdx.x;
    const int t = threadIdx.x;
    const int ui = u[i], vi = v[i], et = etA[i];
    const float ps = psi[et], al = alpha[et], wt = w_t[et];
    const float bb = et ? om1b[0] : om0b[0];
    const float inv = 1.0f / (ps + 1e-7f);
    const float t_i = tarr[i];
    const float* tb = tbar + (size_t)i * N_;
    const float tb_u = tb[ui], tb_v = tb[vi];
    const float cu_h = g_rec[i*8 + et];          // z_u . head_et
    const float cv_h = g_rec[i*8 + 4 + et];      // z_v . head_et
    const float cv_t = g_rec[i*8 + 6 + et];      // z_v . tail_et
    const float* dbase = et ? g_d1 : g_d0;
    const float* ebase = et ? g_e1 : g_e0;
    const float* lgd = et ? g_log_d1 : g_log_d0;
    const float* lge = et ? g_log_e1 : g_log_e0;
    const int nk = 2*i;

    for (int j = t; j < N_; j += 1024) dcur[j] = dbase[j];
    __syncthreads();
    if (t == 0)
        for (int k = 0; k < nk; k++) dcur[g_log_node[k]] = lgd[k];
    __syncthreads();

    // lam_sum over 2N terms, mask j != u_i, j != v_i
    float acc = 0.f;
    for (int j = t; j < N_; j += 1024) {
        if (j == ui || j == vi) continue;
        float d   = dcur[j];
        float tbj = tb[j];
        acc += hawkes_f(cu_h + d + bb, t_i - fmaxf(tb_u, tbj), inv, ps, al, wt);
        acc += hawkes_f(cv_h + d + bb, t_i - fmaxf(tb_v, tbj), inv, ps, al, wt);
    }
    s_red[t] = acc;
    __syncthreads();
    for (int off = 512; off; off >>= 1) {
        if (t < off) s_red[t] += s_red[t+off];
        __syncthreads();
    }
    if (t == 0) out[i*12 + 11] = s_red[0];

    // lam_pos (t==0) and lam_neg (t=1..10)
    if (t < 11) {
        float g, td;
        if (t == 0) {
            g  = cu_h + cv_t + bb;
            td = t_i - fmaxf(tb_u, tb_v);
        } else if (t <= 5) {
            int vn = neg[i*10 + t - 1];
            g  = cu_h + dcur[vn] + bb;
            td = t_i - fmaxf(tb_u, tb[vn]);
        } else {
            int un = neg[i*10 + t - 1];
            float e = ebase[un];
            for (int k = nk - 1; k >= 0; k--)
                if (g_log_node[k] == un) { e = lge[k]; break; }
            g  = e + cv_t + bb;
            td = t_i - fmaxf(tb[un], tb_v);
        }
        out[i*12 + t] = hawkes_f(g, td, inv, ps, al, wt);
    }
}

extern "C" void kernel_launch(void* const* d_in, const int* in_sizes, int n_in,
                              void* d_out, int out_size) {
    const int*   u    = (const int*)  d_in[0];
    const int*   v    = (const int*)  d_in[1];
    const int*   et   = (const int*)  d_in[2];
    const int*   neg  = (const int*)  d_in[3];
    const float* td   = (const float*)d_in[4];
    const float* tbar = (const float*)d_in[5];
    const float* tarr = (const float*)d_in[6];
    const float* z0   = (const float*)d_in[7];
    const float* A    = (const float*)d_in[8];
    const float* S    = (const float*)d_in[9];
    const float* w_t  = (const float*)d_in[10];
    const float* alpha= (const float*)d_in[11];
    const float* psi  = (const float*)d_in[12];
    const float* om0w = (const float*)d_in[13];
    const float* om0b = (const float*)d_in[14];
    const float* om1w = (const float*)d_in[15];
    const float* om1b = (const float*)d_in[16];
    const float* Whw  = (const float*)d_in[17];
    const float* Whb  = (const float*)d_in[18];
    const float* Wsw  = (const float*)d_in[19];
    const float* Wsb  = (const float*)d_in[20];
    const float* Wrw  = (const float*)d_in[21];
    const float* Wrb  = (const float*)d_in[22];
    const float* Wtw  = (const float*)d_in[23];
    const float* Wtb  = (const float*)d_in[24];
    float* out = (float*)d_out;

    const int smem_wh0 = (128*129 + 32*128) * 4;
    const int smem_seq = 2*MAXN*8 + 2*MAXN*4 + 3*128*128*4
                       + (256*3 + 3072 + 512 + 1024 + 800 + 256)*4
                       + (128+128+2+2)*4;

    cudaFuncSetAttribute(k_wh0, cudaFuncAttributeMaxDynamicSharedMemorySize, smem_wh0);
    cudaFuncSetAttribute(k_seq, cudaFuncAttributeMaxDynamicSharedMemorySize, smem_seq);

    k_wh0<<<N_/32, 256, smem_wh0>>>(z0, Whw, Whb);
    k_dots<<<N_/8, 256>>>(z0, om0w, om1w);
    k_finit<<<(N_+1023)/1024, 1024>>>();
    k_nbr<<<2*B_, 512>>>(u, v, A, S);
    k_fset<<<1, 128>>>(u, v);
    k_cmax<<<2*B_, 256>>>();
    k_seq<<<1, 1024, smem_seq>>>(u, v, td, z0, om0w, om1w,
                                 Whw, Whb, Wsw, Wsb, Wrw, Wrb, Wtw, Wtb);
    k_lam<<<B_, 1024>>>(u, v, et, neg, tbar, tarr, w_t, alpha, psi,
                        om0b, om1b, out);
}